// round 10
// baseline (speedup 1.0000x reference)
#include <cuda_runtime.h>
#include <cuda_bf16.h>
#include <cstdint>

#define HID   768
#define HID3  2304
#define SEQ   2048
#define BATCH 8
#define TOK   (BATCH * SEQ)

#define BM 128
#define BN 128
#define BK 64                 // bf16 elems per chunk = 128 B/row
#define NSTAGE 5
#define STAGE_BYTES 32768     // A 16KB + B 16KB
#define SM_TOTAL (NSTAGE * STAGE_BYTES)   // 160 KB -> 1 CTA/SM

// ---------------- scratch (__device__ globals, allocation-free rule) ----------------
__device__ __align__(1024) __nv_bfloat16 g_x_hi[(size_t)TOK * HID];
__device__ __align__(1024) __nv_bfloat16 g_x_lo[(size_t)TOK * HID];
__device__ __align__(1024) __nv_bfloat16 g_w_hi[(size_t)HID3 * HID];
__device__ __align__(1024) __nv_bfloat16 g_w_lo[(size_t)HID3 * HID];
__device__ __align__(1024) __nv_bfloat16 g_q_hi[(size_t)TOK * HID];
__device__ __align__(1024) __nv_bfloat16 g_q_lo[(size_t)TOK * HID];
__device__ __align__(1024) __nv_bfloat16 g_k_hi[(size_t)TOK * HID];
__device__ __align__(1024) __nv_bfloat16 g_k_lo[(size_t)TOK * HID];
__device__ __align__(1024) __nv_bfloat16 g_vT_hi[(size_t)BATCH * HID * SEQ]; // [b][dim][tok]
__device__ __align__(1024) __nv_bfloat16 g_vT_lo[(size_t)BATCH * HID * SEQ];
__device__ __align__(1024) float         g_S[(size_t)BATCH * SEQ * SEQ];
__device__ __align__(1024) __nv_bfloat16 g_P_hi[(size_t)TOK * SEQ];
__device__ __align__(1024) __nv_bfloat16 g_P_lo[(size_t)TOK * SEQ];

// ---------------- PTX helpers (sm_80-era only: legal on plain sm_103) ----------------
__device__ __forceinline__ uint32_t smem_u32(const void* p) {
    uint32_t a;
    asm("{ .reg .u64 t; cvta.to.shared.u64 t, %1; cvt.u32.u64 %0, t; }" : "=r"(a) : "l"(p));
    return a;
}
__device__ __forceinline__ void cp16(uint32_t dst, const void* src) {
    asm volatile("cp.async.cg.shared.global [%0], [%1], 16;"
                 :: "r"(dst), "l"(__cvta_generic_to_global(src)) : "memory");
}
#define CP_COMMIT() asm volatile("cp.async.commit_group;" ::: "memory")
#define CP_WAIT3()  asm volatile("cp.async.wait_group 3;" ::: "memory")

__device__ __forceinline__ void ldsm_x4(uint32_t& d0, uint32_t& d1, uint32_t& d2,
                                        uint32_t& d3, uint32_t addr) {
    asm volatile("ldmatrix.sync.aligned.m8n8.x4.shared.b16 {%0,%1,%2,%3}, [%4];"
                 : "=r"(d0), "=r"(d1), "=r"(d2), "=r"(d3) : "r"(addr));
}
__device__ __forceinline__ void mma16816(float (&c)[4], uint32_t a0, uint32_t a1,
                                         uint32_t a2, uint32_t a3,
                                         uint32_t b0, uint32_t b1) {
    asm volatile("mma.sync.aligned.m16n8k16.row.col.f32.bf16.bf16.f32 "
                 "{%0,%1,%2,%3}, {%4,%5,%6,%7}, {%8,%9}, {%0,%1,%2,%3};"
                 : "+f"(c[0]), "+f"(c[1]), "+f"(c[2]), "+f"(c[3])
                 : "r"(a0), "r"(a1), "r"(a2), "r"(a3), "r"(b0), "r"(b1));
}

__device__ __forceinline__ void split1(float v, __nv_bfloat16& h, __nv_bfloat16& l) {
    h = __float2bfloat16(v);
    l = __float2bfloat16(v - __bfloat162float(h));
}

// ---------------------------------------------------------------------------
// bf16x3 HMMA mainloop. C(128x128 fp32 regs) ~= (Ahi+Alo)(Bhi+Blo)^T via
// hi*hi + lo*hi + hi*lo. A,B K-major rows. 5-stage cp.async pipeline (4 in
// flight), SW128-swizzled smem, register-double-buffered ldmatrix (prefetch
// k16+1 fragments during k16 MMAs). 8 warps: warp tile 32x64.
// ---------------------------------------------------------------------------
__device__ __forceinline__ void run_mainloop(
    const __nv_bfloat16* __restrict__ Ahi, const __nv_bfloat16* __restrict__ Alo, int lda,
    const __nv_bfloat16* __restrict__ Bhi, const __nv_bfloat16* __restrict__ Blo, int ldb,
    int K, int row0, int col0, char* smem, float (&acc)[2][8][4])
{
    const int tid  = threadIdx.x;
    const int lane = tid & 31, wid = tid >> 5;
    const int warp_m = wid >> 1, warp_n = wid & 1;
    const uint32_t sb = smem_u32(smem);

#pragma unroll
    for (int mt = 0; mt < 2; mt++)
#pragma unroll
        for (int nt = 0; nt < 8; nt++)
#pragma unroll
            for (int j = 0; j < 4; j++) acc[mt][nt][j] = 0.f;

    const int NIT = 3 * (K / BK);

    auto issue = [&](int it) {
        const int chunk = it / 3, combo = it - 3 * chunk;
        const __nv_bfloat16* A = (combo == 1) ? Alo : Ahi;
        const __nv_bfloat16* B = (combo == 2) ? Blo : Bhi;
        const int k0 = chunk * BK;
        const uint32_t st = sb + (uint32_t)(it % NSTAGE) * STAGE_BYTES;
#pragma unroll
        for (int w = 0; w < 4; w++) {
            int idx = tid + w * 256, r = idx >> 3, c8 = idx & 7;
            cp16(st + r * 128 + ((c8 ^ (r & 7)) << 4),
                 A + (size_t)(row0 + r) * lda + k0 + c8 * 8);
        }
#pragma unroll
        for (int w = 0; w < 4; w++) {
            int idx = tid + w * 256, r = idx >> 3, c8 = idx & 7;
            cp16(st + 16384 + r * 128 + ((c8 ^ (r & 7)) << 4),
                 B + (size_t)(col0 + r) * ldb + k0 + c8 * 8);
        }
    };

#pragma unroll
    for (int p = 0; p < 4; p++) { issue(p); CP_COMMIT(); }

    // per-thread ldmatrix address invariants
    const int rowA = warp_m * 32 + (lane & 15);     // + mt*16 (keeps r&7)
    const int hA   = lane >> 4, sA7 = rowA & 7;
    const int rB   = warp_n * 64 + (lane & 7) + ((lane >> 4) << 3);  // + p*16
    const int hB   = (lane >> 3) & 1, sB7 = lane & 7;

    uint32_t a[2][2][4], b[2][4][4];

    for (int it = 0; it < NIT; it++) {
        CP_WAIT3();
        __syncthreads();
        if (it + 4 < NIT) issue(it + 4);
        CP_COMMIT();

        const uint32_t sA  = sb + (uint32_t)(it % NSTAGE) * STAGE_BYTES;
        const uint32_t sBs = sA + 16384;

        // prefetch k16 = 0
#pragma unroll
        for (int mt = 0; mt < 2; mt++)
            ldsm_x4(a[0][mt][0], a[0][mt][1], a[0][mt][2], a[0][mt][3],
                    sA + (rowA + mt * 16) * 128 + ((hA ^ sA7) << 4));
#pragma unroll
        for (int p = 0; p < 4; p++)
            ldsm_x4(b[0][p][0], b[0][p][1], b[0][p][2], b[0][p][3],
                    sBs + (rB + p * 16) * 128 + ((hB ^ sB7) << 4));

#pragma unroll
        for (int k16 = 0; k16 < 4; k16++) {
            const int cur = k16 & 1, nxt = cur ^ 1;
            if (k16 < 3) {
#pragma unroll
                for (int mt = 0; mt < 2; mt++)
                    ldsm_x4(a[nxt][mt][0], a[nxt][mt][1], a[nxt][mt][2], a[nxt][mt][3],
                            sA + (rowA + mt * 16) * 128 + ((((k16 + 1) * 2 + hA) ^ sA7) << 4));
#pragma unroll
                for (int p = 0; p < 4; p++)
                    ldsm_x4(b[nxt][p][0], b[nxt][p][1], b[nxt][p][2], b[nxt][p][3],
                            sBs + (rB + p * 16) * 128 + ((((k16 + 1) * 2 + hB) ^ sB7) << 4));
            }
#pragma unroll
            for (int mt = 0; mt < 2; mt++)
#pragma unroll
                for (int nt = 0; nt < 8; nt++)
                    mma16816(acc[mt][nt],
                             a[cur][mt][0], a[cur][mt][1], a[cur][mt][2], a[cur][mt][3],
                             b[cur][nt >> 1][(nt & 1) * 2], b[cur][nt >> 1][(nt & 1) * 2 + 1]);
        }
    }
}

// ---------------- stage 0: fp32 -> bf16 hi/lo split ----------------
__global__ __launch_bounds__(256) void split_kernel(
    const float* __restrict__ src, __nv_bfloat16* __restrict__ hi,
    __nv_bfloat16* __restrict__ lo, int n4)
{
    int i = blockIdx.x * 256 + threadIdx.x;
    if (i >= n4) return;
    float4 v = ((const float4*)src)[i];
    __nv_bfloat16 h0, l0, h1, l1, h2, l2, h3, l3;
    split1(v.x, h0, l0); split1(v.y, h1, l1);
    split1(v.z, h2, l2); split1(v.w, h3, l3);
    __nv_bfloat162* H = (__nv_bfloat162*)hi;
    __nv_bfloat162* L = (__nv_bfloat162*)lo;
    H[2 * i]     = __nv_bfloat162(h0, h1);
    H[2 * i + 1] = __nv_bfloat162(h2, h3);
    L[2 * i]     = __nv_bfloat162(l0, l1);
    L[2 * i + 1] = __nv_bfloat162(l2, l3);
}

// ---------------- stage 1: QKV = x @ W^T + b ----------------
// Per-CTA uniform destination: col blocks 0-5 -> q, 6-11 -> k, 12-17 -> v.
// v tiles are staged in smem and written transposed with coalesced stores.
#define VT_PITCH 136   // bf16 elems; 272 B row pitch (16B aligned)

__global__ __launch_bounds__(256) void qkv_gemm(const float* __restrict__ bias)
{
    extern __shared__ char smem[];
    const int row0 = blockIdx.y * BM;
    const int col0 = blockIdx.x * BN;
    float acc[2][8][4];
    run_mainloop(g_x_hi, g_x_lo, HID, g_w_hi, g_w_lo, HID, HID, row0, col0, smem, acc);

    const int tid = threadIdx.x;
    const int lane = tid & 31, wid = tid >> 5;
    const int warp_m = wid >> 1, warp_n = wid & 1;
    const int quad = lane >> 2, qt = lane & 3;

    if (col0 < 2 * HID) {
        __nv_bfloat16* dh = (col0 < HID) ? g_q_hi : g_k_hi;
        __nv_bfloat16* dl = (col0 < HID) ? g_q_lo : g_k_lo;
        const int cbase = (col0 < HID) ? col0 : (col0 - HID);
#pragma unroll
        for (int mt = 0; mt < 2; mt++)
#pragma unroll
            for (int h = 0; h < 2; h++) {
                const int t = row0 + warp_m * 32 + mt * 16 + quad + h * 8;
#pragma unroll
                for (int nt = 0; nt < 8; nt++) {
                    const int lcol = warp_n * 64 + nt * 8 + qt * 2;
                    float v0 = acc[mt][nt][2 * h]     + __ldg(bias + col0 + lcol);
                    float v1 = acc[mt][nt][2 * h + 1] + __ldg(bias + col0 + lcol + 1);
                    __nv_bfloat16 h0, l0, h1, l1;
                    split1(v0, h0, l0); split1(v1, h1, l1);
                    size_t o = (size_t)t * HID + cbase + lcol;
                    *(__nv_bfloat162*)(dh + o) = __nv_bfloat162(h0, h1);
                    *(__nv_bfloat162*)(dl + o) = __nv_bfloat162(l0, l1);
                }
            }
    } else {
        // ---- v tile: stage transposed hi/lo in smem, then coalesced vT stores ----
        __syncthreads();    // all warps done reading stage buffers
        __nv_bfloat16* svh = (__nv_bfloat16*)smem;                       // [128][VT_PITCH]
        __nv_bfloat16* svl = (__nv_bfloat16*)(smem + 128 * VT_PITCH * 2);
#pragma unroll
        for (int mt = 0; mt < 2; mt++)
#pragma unroll
            for (int h = 0; h < 2; h++) {
                const int r = warp_m * 32 + mt * 16 + quad + h * 8;   // local token
#pragma unroll
                for (int nt = 0; nt < 8; nt++) {
                    const int lcol = warp_n * 64 + nt * 8 + qt * 2;   // local dim
                    float v0 = acc[mt][nt][2 * h]     + __ldg(bias + col0 + lcol);
                    float v1 = acc[mt][nt][2 * h + 1] + __ldg(bias + col0 + lcol + 1);
                    __nv_bfloat16 h0, l0, h1, l1;
                    split1(v0, h0, l0); split1(v1, h1, l1);
                    svh[lcol * VT_PITCH + r] = h0; svl[lcol * VT_PITCH + r] = l0;
                    svh[(lcol + 1) * VT_PITCH + r] = h1; svl[(lcol + 1) * VT_PITCH + r] = l1;
                }
            }
        __syncthreads();
        const int bz = row0 >> 11, tr0 = row0 & 2047;
        const int d0 = col0 - 2 * HID;
        const int d = tid >> 1, half = tid & 1;     // 128 dims x 2 halves
        const size_t go = ((size_t)bz * HID + d0 + d) * SEQ + tr0 + half * 64;
        const uint4* sh4 = (const uint4*)(svh + d * VT_PITCH + half * 64);
        const uint4* sl4 = (const uint4*)(svl + d * VT_PITCH + half * 64);
        uint4* gh4 = (uint4*)(g_vT_hi + go);
        uint4* gl4 = (uint4*)(g_vT_lo + go);
#pragma unroll
        for (int u = 0; u < 8; u++) { gh4[u] = sh4[u]; gl4[u] = sl4[u]; }
    }
}

// ---------------- stage 2: S = q @ k^T (per batch) ----------------
__global__ __launch_bounds__(256) void qk_gemm()
{
    extern __shared__ char smem[];
    const int bz = blockIdx.z;
    const size_t off = (size_t)bz * SEQ * HID;
    const int row0 = blockIdx.y * BM;
    const int col0 = blockIdx.x * BN;
    float acc[2][8][4];
    run_mainloop(g_q_hi + off, g_q_lo + off, HID, g_k_hi + off, g_k_lo + off, HID,
                 HID, row0, col0, smem, acc);

    const int lane = threadIdx.x & 31, wid = threadIdx.x >> 5;
    const int warp_m = wid >> 1, warp_n = wid & 1;
    const int quad = lane >> 2, qt = lane & 3;
#pragma unroll
    for (int mt = 0; mt < 2; mt++)
#pragma unroll
        for (int h = 0; h < 2; h++) {
            const int m = row0 + warp_m * 32 + mt * 16 + quad + h * 8;
            float* Srow = g_S + ((size_t)bz * SEQ + m) * SEQ;
#pragma unroll
            for (int nt = 0; nt < 8; nt++) {
                const int c = col0 + warp_n * 64 + nt * 8 + qt * 2;
                float2 v; v.x = acc[mt][nt][2 * h]; v.y = acc[mt][nt][2 * h + 1];
                *(float2*)(Srow + c) = v;
            }
        }
}

// ---------------- stage 3: softmax + split P ----------------
__global__ __launch_bounds__(256) void softmax_split_kernel()
{
    const size_t row = blockIdx.x;
    const float4* p4 = (const float4*)(g_S + row * SEQ);
    const int tid = threadIdx.x;
    float4 v0 = p4[tid];
    float4 v1 = p4[tid + 256];

    float m = fmaxf(fmaxf(fmaxf(v0.x, v0.y), fmaxf(v0.z, v0.w)),
                    fmaxf(fmaxf(v1.x, v1.y), fmaxf(v1.z, v1.w)));
    __shared__ float red[8], red2[8];
#pragma unroll
    for (int o = 16; o; o >>= 1) m = fmaxf(m, __shfl_xor_sync(0xffffffffu, m, o));
    if ((tid & 31) == 0) red[tid >> 5] = m;
    __syncthreads();
    float bm = red[0];
#pragma unroll
    for (int i = 1; i < 8; i++) bm = fmaxf(bm, red[i]);

    v0.x = __expf(v0.x - bm); v0.y = __expf(v0.y - bm);
    v0.z = __expf(v0.z - bm); v0.w = __expf(v0.w - bm);
    v1.x = __expf(v1.x - bm); v1.y = __expf(v1.y - bm);
    v1.z = __expf(v1.z - bm); v1.w = __expf(v1.w - bm);

    float s = ((v0.x + v0.y) + (v0.z + v0.w)) + ((v1.x + v1.y) + (v1.z + v1.w));
#pragma unroll
    for (int o = 16; o; o >>= 1) s += __shfl_xor_sync(0xffffffffu, s, o);
    if ((tid & 31) == 0) red2[tid >> 5] = s;
    __syncthreads();
    float ts = red2[0];
#pragma unroll
    for (int i = 1; i < 8; i++) ts += red2[i];
    const float inv = 1.0f / ts;

    __nv_bfloat162* PH = (__nv_bfloat162*)(g_P_hi + row * SEQ);
    __nv_bfloat162* PL = (__nv_bfloat162*)(g_P_lo + row * SEQ);
    __nv_bfloat16 h0, l0, h1, l1;
    split1(v0.x * inv, h0, l0); split1(v0.y * inv, h1, l1);
    PH[2 * tid] = __nv_bfloat162(h0, h1); PL[2 * tid] = __nv_bfloat162(l0, l1);
    split1(v0.z * inv, h0, l0); split1(v0.w * inv, h1, l1);
    PH[2 * tid + 1] = __nv_bfloat162(h0, h1); PL[2 * tid + 1] = __nv_bfloat162(l0, l1);
    split1(v1.x * inv, h0, l0); split1(v1.y * inv, h1, l1);
    PH[2 * (tid + 256)] = __nv_bfloat162(h0, h1); PL[2 * (tid + 256)] = __nv_bfloat162(l0, l1);
    split1(v1.z * inv, h0, l0); split1(v1.w * inv, h1, l1);
    PH[2 * (tid + 256) + 1] = __nv_bfloat162(h0, h1); PL[2 * (tid + 256) + 1] = __nv_bfloat162(l0, l1);
}

// ---------------- stage 4: out = P @ v (per batch; B = vT, K-major) ----------------
__global__ __launch_bounds__(256) void pv_gemm(float* __restrict__ out)
{
    extern __shared__ char smem[];
    const int bz = blockIdx.z;
    const size_t pOff = (size_t)bz * SEQ * SEQ;
    const size_t vOff = (size_t)bz * HID * SEQ;
    const int row0 = blockIdx.y * BM;
    const int col0 = blockIdx.x * BN;
    float acc[2][8][4];
    run_mainloop(g_P_hi + pOff, g_P_lo + pOff, SEQ, g_vT_hi + vOff, g_vT_lo + vOff, SEQ,
                 SEQ, row0, col0, smem, acc);

    const int lane = threadIdx.x & 31, wid = threadIdx.x >> 5;
    const int warp_m = wid >> 1, warp_n = wid & 1;
    const int quad = lane >> 2, qt = lane & 3;
#pragma unroll
    for (int mt = 0; mt < 2; mt++)
#pragma unroll
        for (int h = 0; h < 2; h++) {
            const int m = row0 + warp_m * 32 + mt * 16 + quad + h * 8;
            float* Orow = out + ((size_t)bz * SEQ + m) * HID;
#pragma unroll
            for (int nt = 0; nt < 8; nt++) {
                const int c = col0 + warp_n * 64 + nt * 8 + qt * 2;
                float2 v; v.x = acc[mt][nt][2 * h]; v.y = acc[mt][nt][2 * h + 1];
                *(float2*)(Orow + c) = v;
            }
        }
}

// ---------------------------------------------------------------------------
extern "C" void kernel_launch(void* const* d_in, const int* in_sizes, int n_in,
                              void* d_out, int out_size)
{
    const float* x = (const float*)d_in[0];
    const float* W = (const float*)d_in[1];
    const float* b = (const float*)d_in[2];
    float* out = (float*)d_out;
    (void)in_sizes; (void)n_in; (void)out_size;

    cudaFuncSetAttribute(qkv_gemm, cudaFuncAttributeMaxDynamicSharedMemorySize, SM_TOTAL);
    cudaFuncSetAttribute(qk_gemm,  cudaFuncAttributeMaxDynamicSharedMemorySize, SM_TOTAL);
    cudaFuncSetAttribute(pv_gemm,  cudaFuncAttributeMaxDynamicSharedMemorySize, SM_TOTAL);

    __nv_bfloat16 *xh, *xl, *wh, *wl;
    cudaGetSymbolAddress((void**)&xh, g_x_hi); cudaGetSymbolAddress((void**)&xl, g_x_lo);
    cudaGetSymbolAddress((void**)&wh, g_w_hi); cudaGetSymbolAddress((void**)&wl, g_w_lo);

    int nx4 = TOK * HID / 4, nw4 = HID3 * HID / 4;
    split_kernel<<<(nx4 + 255) / 256, 256>>>(x, xh, xl, nx4);
    split_kernel<<<(nw4 + 255) / 256, 256>>>(W, wh, wl, nw4);

    qkv_gemm<<<dim3(HID3 / BN, TOK / BM, 1), 256, SM_TOTAL>>>(b);
    qk_gemm<<<dim3(SEQ / BN, SEQ / BM, BATCH), 256, SM_TOTAL>>>();
    softmax_split_kernel<<<TOK, 256>>>();
    pv_gemm<<<dim3(HID / BN, SEQ / BM, BATCH), 256, SM_TOTAL>>>(out);
}

// round 13
// speedup vs baseline: 1.8423x; 1.8423x over previous
#include <cuda_runtime.h>
#include <cuda_bf16.h>
#include <cstdint>

#define HID   768
#define HID3  2304
#define SEQ   2048
#define BATCH 8
#define TOK   (BATCH * SEQ)

#define BM 128
#define BN 128
#define BK 64                 // bf16 elems per chunk = 128 B/row
#define NSTAGE 3
#define STAGE_BYTES 32768     // A 16KB + B 16KB
#define SM_TOTAL (NSTAGE * STAGE_BYTES)   // 96 KB -> 2 CTAs/SM (the R9 sweet spot)

// ---------------- scratch (__device__ globals, allocation-free rule) ----------------
__device__ __align__(1024) __nv_bfloat16 g_x_hi[(size_t)TOK * HID];
__device__ __align__(1024) __nv_bfloat16 g_x_lo[(size_t)TOK * HID];
__device__ __align__(1024) __nv_bfloat16 g_w_hi[(size_t)HID3 * HID];
__device__ __align__(1024) __nv_bfloat16 g_w_lo[(size_t)HID3 * HID];
__device__ __align__(1024) __nv_bfloat16 g_q_hi[(size_t)TOK * HID];
__device__ __align__(1024) __nv_bfloat16 g_q_lo[(size_t)TOK * HID];
__device__ __align__(1024) __nv_bfloat16 g_k_hi[(size_t)TOK * HID];
__device__ __align__(1024) __nv_bfloat16 g_k_lo[(size_t)TOK * HID];
__device__ __align__(1024) __nv_bfloat16 g_vT_hi[(size_t)BATCH * HID * SEQ]; // [b][dim][tok]
__device__ __align__(1024) __nv_bfloat16 g_vT_lo[(size_t)BATCH * HID * SEQ];
__device__ __align__(1024) float         g_S[(size_t)BATCH * SEQ * SEQ];
__device__ __align__(1024) __nv_bfloat16 g_P_hi[(size_t)TOK * SEQ];
__device__ __align__(1024) __nv_bfloat16 g_P_lo[(size_t)TOK * SEQ];

// ---------------- PTX helpers (sm_80-era only: legal on plain sm_103) ----------------
__device__ __forceinline__ uint32_t smem_u32(const void* p) {
    uint32_t a;
    asm("{ .reg .u64 t; cvta.to.shared.u64 t, %1; cvt.u32.u64 %0, t; }" : "=r"(a) : "l"(p));
    return a;
}
__device__ __forceinline__ void cp16(uint32_t dst, const void* src) {
    asm volatile("cp.async.cg.shared.global [%0], [%1], 16;"
                 :: "r"(dst), "l"(__cvta_generic_to_global(src)) : "memory");
}
#define CP_COMMIT() asm volatile("cp.async.commit_group;" ::: "memory")
#define CP_WAIT1()  asm volatile("cp.async.wait_group 1;" ::: "memory")

__device__ __forceinline__ void ldsm_x4(uint32_t& d0, uint32_t& d1, uint32_t& d2,
                                        uint32_t& d3, uint32_t addr) {
    asm volatile("ldmatrix.sync.aligned.m8n8.x4.shared.b16 {%0,%1,%2,%3}, [%4];"
                 : "=r"(d0), "=r"(d1), "=r"(d2), "=r"(d3) : "r"(addr));
}
__device__ __forceinline__ void mma16816(float (&c)[4], uint32_t a0, uint32_t a1,
                                         uint32_t a2, uint32_t a3,
                                         uint32_t b0, uint32_t b1) {
    asm volatile("mma.sync.aligned.m16n8k16.row.col.f32.bf16.bf16.f32 "
                 "{%0,%1,%2,%3}, {%4,%5,%6,%7}, {%8,%9}, {%0,%1,%2,%3};"
                 : "+f"(c[0]), "+f"(c[1]), "+f"(c[2]), "+f"(c[3])
                 : "r"(a0), "r"(a1), "r"(a2), "r"(a3), "r"(b0), "r"(b1));
}

__device__ __forceinline__ void split1(float v, __nv_bfloat16& h, __nv_bfloat16& l) {
    h = __float2bfloat16(v);
    l = __float2bfloat16(v - __bfloat162float(h));
}

// ---------------------------------------------------------------------------
// bf16x3 HMMA mainloop (R9 configuration: 3-stage cp.async, wait_group 1,
// no register double-buffering -> regs <= 128 -> 2 CTAs/SM).
// C(128x128 fp32 regs) ~= (Ahi+Alo)(Bhi+Blo)^T via hi*hi + lo*hi + hi*lo.
// ---------------------------------------------------------------------------
__device__ __forceinline__ void run_mainloop(
    const __nv_bfloat16* __restrict__ Ahi, const __nv_bfloat16* __restrict__ Alo, int lda,
    const __nv_bfloat16* __restrict__ Bhi, const __nv_bfloat16* __restrict__ Blo, int ldb,
    int K, int row0, int col0, char* smem, float (&acc)[2][8][4])
{
    const int tid  = threadIdx.x;
    const int lane = tid & 31, wid = tid >> 5;
    const int warp_m = wid >> 1, warp_n = wid & 1;
    const uint32_t sb = smem_u32(smem);

#pragma unroll
    for (int mt = 0; mt < 2; mt++)
#pragma unroll
        for (int nt = 0; nt < 8; nt++)
#pragma unroll
            for (int j = 0; j < 4; j++) acc[mt][nt][j] = 0.f;

    const int NIT = 3 * (K / BK);

    auto issue = [&](int it) {
        const int chunk = it / 3, combo = it - 3 * chunk;
        const __nv_bfloat16* A = (combo == 1) ? Alo : Ahi;
        const __nv_bfloat16* B = (combo == 2) ? Blo : Bhi;
        const int k0 = chunk * BK;
        const uint32_t st = sb + (uint32_t)(it % NSTAGE) * STAGE_BYTES;
#pragma unroll
        for (int w = 0; w < 4; w++) {
            int idx = tid + w * 256, r = idx >> 3, c8 = idx & 7;
            cp16(st + r * 128 + ((c8 ^ (r & 7)) << 4),
                 A + (size_t)(row0 + r) * lda + k0 + c8 * 8);
        }
#pragma unroll
        for (int w = 0; w < 4; w++) {
            int idx = tid + w * 256, r = idx >> 3, c8 = idx & 7;
            cp16(st + 16384 + r * 128 + ((c8 ^ (r & 7)) << 4),
                 B + (size_t)(col0 + r) * ldb + k0 + c8 * 8);
        }
    };

    issue(0); CP_COMMIT();
    issue(1); CP_COMMIT();

    // per-thread ldmatrix address invariants
    const int rowA = warp_m * 32 + (lane & 15);     // + mt*16 (keeps r&7)
    const int hA   = lane >> 4, sA7 = rowA & 7;
    const int rB   = warp_n * 64 + (lane & 7) + ((lane >> 4) << 3);  // + p*16
    const int hB   = (lane >> 3) & 1, sB7 = lane & 7;

    for (int it = 0; it < NIT; it++) {
        CP_WAIT1();
        __syncthreads();
        if (it + 2 < NIT) issue(it + 2);
        CP_COMMIT();

        const uint32_t sA  = sb + (uint32_t)(it % NSTAGE) * STAGE_BYTES;
        const uint32_t sBs = sA + 16384;
#pragma unroll
        for (int k16 = 0; k16 < 4; k16++) {
            uint32_t a[2][4], b[4][4];
#pragma unroll
            for (int mt = 0; mt < 2; mt++)
                ldsm_x4(a[mt][0], a[mt][1], a[mt][2], a[mt][3],
                        sA + (rowA + mt * 16) * 128 + (((k16 * 2 + hA) ^ sA7) << 4));
#pragma unroll
            for (int p = 0; p < 4; p++)
                ldsm_x4(b[p][0], b[p][1], b[p][2], b[p][3],
                        sBs + (rB + p * 16) * 128 + (((k16 * 2 + hB) ^ sB7) << 4));
#pragma unroll
            for (int mt = 0; mt < 2; mt++)
#pragma unroll
                for (int nt = 0; nt < 8; nt++)
                    mma16816(acc[mt][nt], a[mt][0], a[mt][1], a[mt][2], a[mt][3],
                             b[nt >> 1][(nt & 1) * 2], b[nt >> 1][(nt & 1) * 2 + 1]);
        }
    }
}

// ---------------- stage 0: fp32 -> bf16 hi/lo split ----------------
__global__ __launch_bounds__(256) void split_kernel(
    const float* __restrict__ src, __nv_bfloat16* __restrict__ hi,
    __nv_bfloat16* __restrict__ lo, int n4)
{
    int i = blockIdx.x * 256 + threadIdx.x;
    if (i >= n4) return;
    float4 v = ((const float4*)src)[i];
    __nv_bfloat16 h0, l0, h1, l1, h2, l2, h3, l3;
    split1(v.x, h0, l0); split1(v.y, h1, l1);
    split1(v.z, h2, l2); split1(v.w, h3, l3);
    __nv_bfloat162* H = (__nv_bfloat162*)hi;
    __nv_bfloat162* L = (__nv_bfloat162*)lo;
    H[2 * i]     = __nv_bfloat162(h0, h1);
    H[2 * i + 1] = __nv_bfloat162(h2, h3);
    L[2 * i]     = __nv_bfloat162(l0, l1);
    L[2 * i + 1] = __nv_bfloat162(l2, l3);
}

// ---------------- stage 1: QKV = x @ W^T + b ----------------
// Per-CTA uniform destination: col blocks 0-5 -> q, 6-11 -> k, 12-17 -> v.
// v tiles are staged in smem and written transposed with coalesced stores.
#define VT_PITCH 136   // bf16 elems; 272 B row pitch (16B aligned, conflict-skewed)

__global__ __launch_bounds__(256) void qkv_gemm(const float* __restrict__ bias)
{
    extern __shared__ char smem[];
    const int row0 = blockIdx.y * BM;
    const int col0 = blockIdx.x * BN;
    float acc[2][8][4];
    run_mainloop(g_x_hi, g_x_lo, HID, g_w_hi, g_w_lo, HID, HID, row0, col0, smem, acc);

    const int tid = threadIdx.x;
    const int lane = tid & 31, wid = tid >> 5;
    const int warp_m = wid >> 1, warp_n = wid & 1;
    const int quad = lane >> 2, qt = lane & 3;

    if (col0 < 2 * HID) {
        __nv_bfloat16* dh = (col0 < HID) ? g_q_hi : g_k_hi;
        __nv_bfloat16* dl = (col0 < HID) ? g_q_lo : g_k_lo;
        const int cbase = (col0 < HID) ? col0 : (col0 - HID);
#pragma unroll
        for (int mt = 0; mt < 2; mt++)
#pragma unroll
            for (int h = 0; h < 2; h++) {
                const int t = row0 + warp_m * 32 + mt * 16 + quad + h * 8;
#pragma unroll
                for (int nt = 0; nt < 8; nt++) {
                    const int lcol = warp_n * 64 + nt * 8 + qt * 2;
                    float v0 = acc[mt][nt][2 * h]     + __ldg(bias + col0 + lcol);
                    float v1 = acc[mt][nt][2 * h + 1] + __ldg(bias + col0 + lcol + 1);
                    __nv_bfloat16 h0, l0, h1, l1;
                    split1(v0, h0, l0); split1(v1, h1, l1);
                    size_t o = (size_t)t * HID + cbase + lcol;
                    *(__nv_bfloat162*)(dh + o) = __nv_bfloat162(h0, h1);
                    *(__nv_bfloat162*)(dl + o) = __nv_bfloat162(l0, l1);
                }
            }
    } else {
        // ---- v tile: stage transposed hi/lo in smem, then coalesced vT stores ----
        __syncthreads();    // all warps done reading stage buffers
        __nv_bfloat16* svh = (__nv_bfloat16*)smem;                       // [128][VT_PITCH]
        __nv_bfloat16* svl = (__nv_bfloat16*)(smem + 128 * VT_PITCH * 2);
#pragma unroll
        for (int mt = 0; mt < 2; mt++)
#pragma unroll
            for (int h = 0; h < 2; h++) {
                const int r = warp_m * 32 + mt * 16 + quad + h * 8;   // local token
#pragma unroll
                for (int nt = 0; nt < 8; nt++) {
                    const int lcol = warp_n * 64 + nt * 8 + qt * 2;   // local dim
                    float v0 = acc[mt][nt][2 * h]     + __ldg(bias + col0 + lcol);
                    float v1 = acc[mt][nt][2 * h + 1] + __ldg(bias + col0 + lcol + 1);
                    __nv_bfloat16 h0, l0, h1, l1;
                    split1(v0, h0, l0); split1(v1, h1, l1);
                    svh[lcol * VT_PITCH + r] = h0; svl[lcol * VT_PITCH + r] = l0;
                    svh[(lcol + 1) * VT_PITCH + r] = h1; svl[(lcol + 1) * VT_PITCH + r] = l1;
                }
            }
        __syncthreads();
        const int bz = row0 >> 11, tr0 = row0 & 2047;
        const int d0 = col0 - 2 * HID;
        const int d = tid >> 1, half = tid & 1;     // 128 dims x 2 64-tok halves
        const size_t go = ((size_t)bz * HID + d0 + d) * SEQ + tr0 + half * 64;
        const uint4* sh4 = (const uint4*)(svh + d * VT_PITCH + half * 64);
        const uint4* sl4 = (const uint4*)(svl + d * VT_PITCH + half * 64);
        uint4* gh4 = (uint4*)(g_vT_hi + go);
        uint4* gl4 = (uint4*)(g_vT_lo + go);
#pragma unroll
        for (int u = 0; u < 8; u++) { gh4[u] = sh4[u]; gl4[u] = sl4[u]; }
    }
}

// ---------------- stage 2: S = q @ k^T (per batch) ----------------
__global__ __launch_bounds__(256) void qk_gemm()
{
    extern __shared__ char smem[];
    const int bz = blockIdx.z;
    const size_t off = (size_t)bz * SEQ * HID;
    const int row0 = blockIdx.y * BM;
    const int col0 = blockIdx.x * BN;
    float acc[2][8][4];
    run_mainloop(g_q_hi + off, g_q_lo + off, HID, g_k_hi + off, g_k_lo + off, HID,
                 HID, row0, col0, smem, acc);

    const int lane = threadIdx.x & 31, wid = threadIdx.x >> 5;
    const int warp_m = wid >> 1, warp_n = wid & 1;
    const int quad = lane >> 2, qt = lane & 3;
#pragma unroll
    for (int mt = 0; mt < 2; mt++)
#pragma unroll
        for (int h = 0; h < 2; h++) {
            const int m = row0 + warp_m * 32 + mt * 16 + quad + h * 8;
            float* Srow = g_S + ((size_t)bz * SEQ + m) * SEQ;
#pragma unroll
            for (int nt = 0; nt < 8; nt++) {
                const int c = col0 + warp_n * 64 + nt * 8 + qt * 2;
                float2 v; v.x = acc[mt][nt][2 * h]; v.y = acc[mt][nt][2 * h + 1];
                *(float2*)(Srow + c) = v;
            }
        }
}

// ---------------- stage 3: softmax + split P ----------------
__global__ __launch_bounds__(256) void softmax_split_kernel()
{
    const size_t row = blockIdx.x;
    const float4* p4 = (const float4*)(g_S + row * SEQ);
    const int tid = threadIdx.x;
    float4 v0 = p4[tid];
    float4 v1 = p4[tid + 256];

    float m = fmaxf(fmaxf(fmaxf(v0.x, v0.y), fmaxf(v0.z, v0.w)),
                    fmaxf(fmaxf(v1.x, v1.y), fmaxf(v1.z, v1.w)));
    __shared__ float red[8], red2[8];
#pragma unroll
    for (int o = 16; o; o >>= 1) m = fmaxf(m, __shfl_xor_sync(0xffffffffu, m, o));
    if ((tid & 31) == 0) red[tid >> 5] = m;
    __syncthreads();
    float bm = red[0];
#pragma unroll
    for (int i = 1; i < 8; i++) bm = fmaxf(bm, red[i]);

    v0.x = __expf(v0.x - bm); v0.y = __expf(v0.y - bm);
    v0.z = __expf(v0.z - bm); v0.w = __expf(v0.w - bm);
    v1.x = __expf(v1.x - bm); v1.y = __expf(v1.y - bm);
    v1.z = __expf(v1.z - bm); v1.w = __expf(v1.w - bm);

    float s = ((v0.x + v0.y) + (v0.z + v0.w)) + ((v1.x + v1.y) + (v1.z + v1.w));
#pragma unroll
    for (int o = 16; o; o >>= 1) s += __shfl_xor_sync(0xffffffffu, s, o);
    if ((tid & 31) == 0) red2[tid >> 5] = s;
    __syncthreads();
    float ts = red2[0];
#pragma unroll
    for (int i = 1; i < 8; i++) ts += red2[i];
    const float inv = 1.0f / ts;

    __nv_bfloat162* PH = (__nv_bfloat162*)(g_P_hi + row * SEQ);
    __nv_bfloat162* PL = (__nv_bfloat162*)(g_P_lo + row * SEQ);
    __nv_bfloat16 h0, l0, h1, l1;
    split1(v0.x * inv, h0, l0); split1(v0.y * inv, h1, l1);
    PH[2 * tid] = __nv_bfloat162(h0, h1); PL[2 * tid] = __nv_bfloat162(l0, l1);
    split1(v0.z * inv, h0, l0); split1(v0.w * inv, h1, l1);
    PH[2 * tid + 1] = __nv_bfloat162(h0, h1); PL[2 * tid + 1] = __nv_bfloat162(l0, l1);
    split1(v1.x * inv, h0, l0); split1(v1.y * inv, h1, l1);
    PH[2 * (tid + 256)] = __nv_bfloat162(h0, h1); PL[2 * (tid + 256)] = __nv_bfloat162(l0, l1);
    split1(v1.z * inv, h0, l0); split1(v1.w * inv, h1, l1);
    PH[2 * (tid + 256) + 1] = __nv_bfloat162(h0, h1); PL[2 * (tid + 256) + 1] = __nv_bfloat162(l0, l1);
}

// ---------------- stage 4: out = P @ v (per batch; B = vT, K-major) ----------------
__global__ __launch_bounds__(256) void pv_gemm(float* __restrict__ out)
{
    extern __shared__ char smem[];
    const int bz = blockIdx.z;
    const size_t pOff = (size_t)bz * SEQ * SEQ;
    const size_t vOff = (size_t)bz * HID * SEQ;
    const int row0 = blockIdx.y * BM;
    const int col0 = blockIdx.x * BN;
    float acc[2][8][4];
    run_mainloop(g_P_hi + pOff, g_P_lo + pOff, SEQ, g_vT_hi + vOff, g_vT_lo + vOff, SEQ,
                 SEQ, row0, col0, smem, acc);

    const int lane = threadIdx.x & 31, wid = threadIdx.x >> 5;
    const int warp_m = wid >> 1, warp_n = wid & 1;
    const int quad = lane >> 2, qt = lane & 3;
#pragma unroll
    for (int mt = 0; mt < 2; mt++)
#pragma unroll
        for (int h = 0; h < 2; h++) {
            const int m = row0 + warp_m * 32 + mt * 16 + quad + h * 8;
            float* Orow = out + ((size_t)bz * SEQ + m) * HID;
#pragma unroll
            for (int nt = 0; nt < 8; nt++) {
                const int c = col0 + warp_n * 64 + nt * 8 + qt * 2;
                float2 v; v.x = acc[mt][nt][2 * h]; v.y = acc[mt][nt][2 * h + 1];
                *(float2*)(Orow + c) = v;
            }
        }
}

// ---------------------------------------------------------------------------
extern "C" void kernel_launch(void* const* d_in, const int* in_sizes, int n_in,
                              void* d_out, int out_size)
{
    const float* x = (const float*)d_in[0];
    const float* W = (const float*)d_in[1];
    const float* b = (const float*)d_in[2];
    float* out = (float*)d_out;
    (void)in_sizes; (void)n_in; (void)out_size;

    cudaFuncSetAttribute(qkv_gemm, cudaFuncAttributeMaxDynamicSharedMemorySize, SM_TOTAL);
    cudaFuncSetAttribute(qk_gemm,  cudaFuncAttributeMaxDynamicSharedMemorySize, SM_TOTAL);
    cudaFuncSetAttribute(pv_gemm,  cudaFuncAttributeMaxDynamicSharedMemorySize, SM_TOTAL);

    __nv_bfloat16 *xh, *xl, *wh, *wl;
    cudaGetSymbolAddress((void**)&xh, g_x_hi); cudaGetSymbolAddress((void**)&xl, g_x_lo);
    cudaGetSymbolAddress((void**)&wh, g_w_hi); cudaGetSymbolAddress((void**)&wl, g_w_lo);

    int nx4 = TOK * HID / 4, nw4 = HID3 * HID / 4;
    split_kernel<<<(nx4 + 255) / 256, 256>>>(x, xh, xl, nx4);
    split_kernel<<<(nw4 + 255) / 256, 256>>>(W, wh, wl, nw4);

    qkv_gemm<<<dim3(HID3 / BN, TOK / BM, 1), 256, SM_TOTAL>>>(b);
    qk_gemm<<<dim3(SEQ / BN, SEQ / BM, BATCH), 256, SM_TOTAL>>>();
    softmax_split_kernel<<<TOK, 256>>>();
    pv_gemm<<<dim3(HID / BN, SEQ / BM, BATCH), 256, SM_TOTAL>>>(out);
}

// round 14
// speedup vs baseline: 2.1726x; 1.1793x over previous
#include <cuda_runtime.h>
#include <cuda_bf16.h>
#include <cuda_fp16.h>
#include <cstdint>

#define HID   768
#define HID3  2304
#define SEQ   2048
#define BATCH 8
#define TOK   (BATCH * SEQ)

#define BM 128
#define BN 128
#define BK 64                 // 16-bit elems per chunk = 128 B/row
#define NSTAGE 3
#define STAGE_BYTES 32768     // A 16KB + B 16KB
#define SM_TOTAL (NSTAGE * STAGE_BYTES)   // 96 KB -> 2 CTAs/SM (proven sweet spot)

// ---------------- scratch (__device__ globals, allocation-free rule) ----------------
__device__ __align__(1024) __nv_bfloat16 g_x_hi[(size_t)TOK * HID];
__device__ __align__(1024) __nv_bfloat16 g_x_lo[(size_t)TOK * HID];
__device__ __align__(1024) __nv_bfloat16 g_w_hi[(size_t)HID3 * HID];
__device__ __align__(1024) __nv_bfloat16 g_w_lo[(size_t)HID3 * HID];
__device__ __align__(1024) __nv_bfloat16 g_q_hi[(size_t)TOK * HID];
__device__ __align__(1024) __nv_bfloat16 g_q_lo[(size_t)TOK * HID];
__device__ __align__(1024) __nv_bfloat16 g_k_hi[(size_t)TOK * HID];
__device__ __align__(1024) __nv_bfloat16 g_k_lo[(size_t)TOK * HID];
__device__ __align__(1024) __half        g_vT_hi[(size_t)BATCH * HID * SEQ]; // [b][dim][tok] fp16
__device__ __align__(1024) __half        g_vT_lo[(size_t)BATCH * HID * SEQ];
__device__ __align__(1024) float         g_S[(size_t)BATCH * SEQ * SEQ];
__device__ __align__(1024) __half        g_P[(size_t)TOK * SEQ];             // fp16, single
// ---------------- PTX helpers (sm_80-era only: legal on plain sm_103) ----------------
__device__ __forceinline__ uint32_t smem_u32(const void* p) {
    uint32_t a;
    asm("{ .reg .u64 t; cvta.to.shared.u64 t, %1; cvt.u32.u64 %0, t; }" : "=r"(a) : "l"(p));
    return a;
}
__device__ __forceinline__ void cp16(uint32_t dst, const void* src) {
    asm volatile("cp.async.cg.shared.global [%0], [%1], 16;"
                 :: "r"(dst), "l"(__cvta_generic_to_global(src)) : "memory");
}
#define CP_COMMIT() asm volatile("cp.async.commit_group;" ::: "memory")
#define CP_WAIT1()  asm volatile("cp.async.wait_group 1;" ::: "memory")

__device__ __forceinline__ void ldsm_x4(uint32_t& d0, uint32_t& d1, uint32_t& d2,
                                        uint32_t& d3, uint32_t addr) {
    asm volatile("ldmatrix.sync.aligned.m8n8.x4.shared.b16 {%0,%1,%2,%3}, [%4];"
                 : "=r"(d0), "=r"(d1), "=r"(d2), "=r"(d3) : "r"(addr));
}
template <bool FP16>
__device__ __forceinline__ void mma16816(float (&c)[4], uint32_t a0, uint32_t a1,
                                         uint32_t a2, uint32_t a3,
                                         uint32_t b0, uint32_t b1) {
    if (FP16)
        asm volatile("mma.sync.aligned.m16n8k16.row.col.f32.f16.f16.f32 "
                     "{%0,%1,%2,%3}, {%4,%5,%6,%7}, {%8,%9}, {%0,%1,%2,%3};"
                     : "+f"(c[0]), "+f"(c[1]), "+f"(c[2]), "+f"(c[3])
                     : "r"(a0), "r"(a1), "r"(a2), "r"(a3), "r"(b0), "r"(b1));
    else
        asm volatile("mma.sync.aligned.m16n8k16.row.col.f32.bf16.bf16.f32 "
                     "{%0,%1,%2,%3}, {%4,%5,%6,%7}, {%8,%9}, {%0,%1,%2,%3};"
                     : "+f"(c[0]), "+f"(c[1]), "+f"(c[2]), "+f"(c[3])
                     : "r"(a0), "r"(a1), "r"(a2), "r"(a3), "r"(b0), "r"(b1));
}

__device__ __forceinline__ void split1(float v, __nv_bfloat16& h, __nv_bfloat16& l) {
    h = __float2bfloat16(v);
    l = __float2bfloat16(v - __bfloat162float(h));
}
__device__ __forceinline__ void split1h(float v, __half& h, __half& l) {
    h = __float2half(v);
    l = __float2half(v - __half2float(h));
}

// ---------------------------------------------------------------------------
// Split-GEMM HMMA mainloop (R13-proven config: 3-stage cp.async, wait_group 1,
// regs <= 128 -> 2 CTAs/SM). NCOMBO=3 (bf16x3): (A0,B0),(A1,B0),(A0,B1).
// NCOMBO=2 (fp16x2, PV): (A0,B0),(A0,B1). Operands are 16-bit, K-major rows.
// ---------------------------------------------------------------------------
template <int NCOMBO, bool FP16>
__device__ __forceinline__ void run_mainloop(
    const uint8_t* __restrict__ A0, const uint8_t* __restrict__ A1, int lda,
    const uint8_t* __restrict__ B0, const uint8_t* __restrict__ B1, int ldb,
    int K, int row0, int col0, char* smem, float (&acc)[2][8][4])
{
    const int tid  = threadIdx.x;
    const int lane = tid & 31, wid = tid >> 5;
    const int warp_m = wid >> 1, warp_n = wid & 1;
    const uint32_t sb = smem_u32(smem);

#pragma unroll
    for (int mt = 0; mt < 2; mt++)
#pragma unroll
        for (int nt = 0; nt < 8; nt++)
#pragma unroll
            for (int j = 0; j < 4; j++) acc[mt][nt][j] = 0.f;

    const int NIT = NCOMBO * (K / BK);

    auto issue = [&](int it) {
        const int chunk = it / NCOMBO, combo = it - NCOMBO * chunk;
        const uint8_t* A = (NCOMBO == 3 && combo == 1) ? A1 : A0;
        const uint8_t* B = (combo == NCOMBO - 1) ? B1 : B0;
        const size_t k0b = (size_t)chunk * BK * 2;      // byte offset in K
        const uint32_t st = sb + (uint32_t)(it % NSTAGE) * STAGE_BYTES;
#pragma unroll
        for (int w = 0; w < 4; w++) {
            int idx = tid + w * 256, r = idx >> 3, c8 = idx & 7;
            cp16(st + r * 128 + ((c8 ^ (r & 7)) << 4),
                 A + (size_t)(row0 + r) * lda * 2 + k0b + c8 * 16);
        }
#pragma unroll
        for (int w = 0; w < 4; w++) {
            int idx = tid + w * 256, r = idx >> 3, c8 = idx & 7;
            cp16(st + 16384 + r * 128 + ((c8 ^ (r & 7)) << 4),
                 B + (size_t)(col0 + r) * ldb * 2 + k0b + c8 * 16);
        }
    };

    issue(0); CP_COMMIT();
    issue(1); CP_COMMIT();

    // per-thread ldmatrix address invariants
    const int rowA = warp_m * 32 + (lane & 15);     // + mt*16 (keeps r&7)
    const int hA   = lane >> 4, sA7 = rowA & 7;
    const int rB   = warp_n * 64 + (lane & 7) + ((lane >> 4) << 3);  // + p*16
    const int hB   = (lane >> 3) & 1, sB7 = lane & 7;

    for (int it = 0; it < NIT; it++) {
        CP_WAIT1();
        __syncthreads();
        if (it + 2 < NIT) issue(it + 2);
        CP_COMMIT();

        const uint32_t sA  = sb + (uint32_t)(it % NSTAGE) * STAGE_BYTES;
        const uint32_t sBs = sA + 16384;
#pragma unroll
        for (int k16 = 0; k16 < 4; k16++) {
            uint32_t a[2][4], b[4][4];
#pragma unroll
            for (int mt = 0; mt < 2; mt++)
                ldsm_x4(a[mt][0], a[mt][1], a[mt][2], a[mt][3],
                        sA + (rowA + mt * 16) * 128 + (((k16 * 2 + hA) ^ sA7) << 4));
#pragma unroll
            for (int p = 0; p < 4; p++)
                ldsm_x4(b[p][0], b[p][1], b[p][2], b[p][3],
                        sBs + (rB + p * 16) * 128 + (((k16 * 2 + hB) ^ sB7) << 4));
#pragma unroll
            for (int mt = 0; mt < 2; mt++)
#pragma unroll
                for (int nt = 0; nt < 8; nt++)
                    mma16816<FP16>(acc[mt][nt], a[mt][0], a[mt][1], a[mt][2], a[mt][3],
                                   b[nt >> 1][(nt & 1) * 2], b[nt >> 1][(nt & 1) * 2 + 1]);
        }
    }
}

// ---------------- stage 0: fp32 -> bf16 hi/lo split ----------------
__global__ __launch_bounds__(256) void split_kernel(
    const float* __restrict__ src, __nv_bfloat16* __restrict__ hi,
    __nv_bfloat16* __restrict__ lo, int n4)
{
    int i = blockIdx.x * 256 + threadIdx.x;
    if (i >= n4) return;
    float4 v = ((const float4*)src)[i];
    __nv_bfloat16 h0, l0, h1, l1, h2, l2, h3, l3;
    split1(v.x, h0, l0); split1(v.y, h1, l1);
    split1(v.z, h2, l2); split1(v.w, h3, l3);
    __nv_bfloat162* H = (__nv_bfloat162*)hi;
    __nv_bfloat162* L = (__nv_bfloat162*)lo;
    H[2 * i]     = __nv_bfloat162(h0, h1);
    H[2 * i + 1] = __nv_bfloat162(h2, h3);
    L[2 * i]     = __nv_bfloat162(l0, l1);
    L[2 * i + 1] = __nv_bfloat162(l2, l3);
}

// ---------------- stage 1: QKV = x @ W^T + b ----------------
// Per-CTA uniform destination: col blocks -> q / k / v. v tiles staged in smem
// (fp16 hi/lo) and written transposed with coalesced stores.
#define VT_PITCH 136   // elems; 272 B row pitch (16B aligned, conflict-skewed)

__global__ __launch_bounds__(256) void qkv_gemm(const float* __restrict__ bias)
{
    extern __shared__ char smem[];
    const int row0 = blockIdx.y * BM;
    const int col0 = blockIdx.x * BN;
    float acc[2][8][4];
    run_mainloop<3, false>((const uint8_t*)g_x_hi, (const uint8_t*)g_x_lo, HID,
                           (const uint8_t*)g_w_hi, (const uint8_t*)g_w_lo, HID,
                           HID, row0, col0, smem, acc);

    const int tid = threadIdx.x;
    const int lane = tid & 31, wid = tid >> 5;
    const int warp_m = wid >> 1, warp_n = wid & 1;
    const int quad = lane >> 2, qt = lane & 3;

    if (col0 < 2 * HID) {
        __nv_bfloat16* dh = (col0 < HID) ? g_q_hi : g_k_hi;
        __nv_bfloat16* dl = (col0 < HID) ? g_q_lo : g_k_lo;
        const int cbase = (col0 < HID) ? col0 : (col0 - HID);
#pragma unroll
        for (int mt = 0; mt < 2; mt++)
#pragma unroll
            for (int h = 0; h < 2; h++) {
                const int t = row0 + warp_m * 32 + mt * 16 + quad + h * 8;
#pragma unroll
                for (int nt = 0; nt < 8; nt++) {
                    const int lcol = warp_n * 64 + nt * 8 + qt * 2;
                    float v0 = acc[mt][nt][2 * h]     + __ldg(bias + col0 + lcol);
                    float v1 = acc[mt][nt][2 * h + 1] + __ldg(bias + col0 + lcol + 1);
                    __nv_bfloat16 h0, l0, h1, l1;
                    split1(v0, h0, l0); split1(v1, h1, l1);
                    size_t o = (size_t)t * HID + cbase + lcol;
                    *(__nv_bfloat162*)(dh + o) = __nv_bfloat162(h0, h1);
                    *(__nv_bfloat162*)(dl + o) = __nv_bfloat162(l0, l1);
                }
            }
    } else {
        // ---- v tile: stage transposed fp16 hi/lo in smem, coalesced vT stores ----
        __syncthreads();    // all warps done reading stage buffers
        __half* svh = (__half*)smem;                          // [128][VT_PITCH]
        __half* svl = (__half*)(smem + 128 * VT_PITCH * 2);
#pragma unroll
        for (int mt = 0; mt < 2; mt++)
#pragma unroll
            for (int h = 0; h < 2; h++) {
                const int r = warp_m * 32 + mt * 16 + quad + h * 8;   // local token
#pragma unroll
                for (int nt = 0; nt < 8; nt++) {
                    const int lcol = warp_n * 64 + nt * 8 + qt * 2;   // local dim
                    float v0 = acc[mt][nt][2 * h]     + __ldg(bias + col0 + lcol);
                    float v1 = acc[mt][nt][2 * h + 1] + __ldg(bias + col0 + lcol + 1);
                    __half h0, l0, h1, l1;
                    split1h(v0, h0, l0); split1h(v1, h1, l1);
                    svh[lcol * VT_PITCH + r] = h0; svl[lcol * VT_PITCH + r] = l0;
                    svh[(lcol + 1) * VT_PITCH + r] = h1; svl[(lcol + 1) * VT_PITCH + r] = l1;
                }
            }
        __syncthreads();
        const int bz = row0 >> 11, tr0 = row0 & 2047;
        const int d0 = col0 - 2 * HID;
        const int d = tid >> 1, half_ = tid & 1;     // 128 dims x 2 64-tok halves
        const size_t go = ((size_t)bz * HID + d0 + d) * SEQ + tr0 + half_ * 64;
        const uint4* sh4 = (const uint4*)(svh + d * VT_PITCH + half_ * 64);
        const uint4* sl4 = (const uint4*)(svl + d * VT_PITCH + half_ * 64);
        uint4* gh4 = (uint4*)(g_vT_hi + go);
        uint4* gl4 = (uint4*)(g_vT_lo + go);
#pragma unroll
        for (int u = 0; u < 8; u++) { gh4[u] = sh4[u]; gl4[u] = sl4[u]; }
    }
}

// ---------------- stage 2: S = q @ k^T (per batch) ----------------
__global__ __launch_bounds__(256) void qk_gemm()
{
    extern __shared__ char smem[];
    const int bz = blockIdx.z;
    const size_t off = (size_t)bz * SEQ * HID;
    const int row0 = blockIdx.y * BM;
    const int col0 = blockIdx.x * BN;
    float acc[2][8][4];
    run_mainloop<3, false>((const uint8_t*)(g_q_hi + off), (const uint8_t*)(g_q_lo + off), HID,
                           (const uint8_t*)(g_k_hi + off), (const uint8_t*)(g_k_lo + off), HID,
                           HID, row0, col0, smem, acc);

    const int lane = threadIdx.x & 31, wid = threadIdx.x >> 5;
    const int warp_m = wid >> 1, warp_n = wid & 1;
    const int quad = lane >> 2, qt = lane & 3;
#pragma unroll
    for (int mt = 0; mt < 2; mt++)
#pragma unroll
        for (int h = 0; h < 2; h++) {
            const int m = row0 + warp_m * 32 + mt * 16 + quad + h * 8;
            float* Srow = g_S + ((size_t)bz * SEQ + m) * SEQ;
#pragma unroll
            for (int nt = 0; nt < 8; nt++) {
                const int c = col0 + warp_n * 64 + nt * 8 + qt * 2;
                float2 v; v.x = acc[mt][nt][2 * h]; v.y = acc[mt][nt][2 * h + 1];
                *(float2*)(Srow + c) = v;
            }
        }
}

// ---------------- stage 3: softmax -> fp16 P (single array) ----------------
__global__ __launch_bounds__(256) void softmax_split_kernel()
{
    const size_t row = blockIdx.x;
    const float4* p4 = (const float4*)(g_S + row * SEQ);
    const int tid = threadIdx.x;
    float4 v0 = p4[tid];
    float4 v1 = p4[tid + 256];

    float m = fmaxf(fmaxf(fmaxf(v0.x, v0.y), fmaxf(v0.z, v0.w)),
                    fmaxf(fmaxf(v1.x, v1.y), fmaxf(v1.z, v1.w)));
    __shared__ float red[8], red2[8];
#pragma unroll
    for (int o = 16; o; o >>= 1) m = fmaxf(m, __shfl_xor_sync(0xffffffffu, m, o));
    if ((tid & 31) == 0) red[tid >> 5] = m;
    __syncthreads();
    float bm = red[0];
#pragma unroll
    for (int i = 1; i < 8; i++) bm = fmaxf(bm, red[i]);

    v0.x = __expf(v0.x - bm); v0.y = __expf(v0.y - bm);
    v0.z = __expf(v0.z - bm); v0.w = __expf(v0.w - bm);
    v1.x = __expf(v1.x - bm); v1.y = __expf(v1.y - bm);
    v1.z = __expf(v1.z - bm); v1.w = __expf(v1.w - bm);

    float s = ((v0.x + v0.y) + (v0.z + v0.w)) + ((v1.x + v1.y) + (v1.z + v1.w));
#pragma unroll
    for (int o = 16; o; o >>= 1) s += __shfl_xor_sync(0xffffffffu, s, o);
    if ((tid & 31) == 0) red2[tid >> 5] = s;
    __syncthreads();
    float ts = red2[0];
#pragma unroll
    for (int i = 1; i < 8; i++) ts += red2[i];
    const float inv = 1.0f / ts;

    __half2* P2 = (__half2*)(g_P + row * SEQ);
    P2[2 * tid]     = __floats2half2_rn(v0.x * inv, v0.y * inv);
    P2[2 * tid + 1] = __floats2half2_rn(v0.z * inv, v0.w * inv);
    P2[2 * (tid + 256)]     = __floats2half2_rn(v1.x * inv, v1.y * inv);
    P2[2 * (tid + 256) + 1] = __floats2half2_rn(v1.z * inv, v1.w * inv);
}

// ---------------- stage 4: out = P @ v (fp16 x2: P*V_hi + P*V_lo) ----------------
__global__ __launch_bounds__(256) void pv_gemm(float* __restrict__ out)
{
    extern __shared__ char smem[];
    const int bz = blockIdx.z;
    const size_t pOff = (size_t)bz * SEQ * SEQ;
    const size_t vOff = (size_t)bz * HID * SEQ;
    const int row0 = blockIdx.y * BM;
    const int col0 = blockIdx.x * BN;
    float acc[2][8][4];
    run_mainloop<2, true>((const uint8_t*)(g_P + pOff), nullptr, SEQ,
                          (const uint8_t*)(g_vT_hi + vOff), (const uint8_t*)(g_vT_lo + vOff), SEQ,
                          SEQ, row0, col0, smem, acc);

    const int lane = threadIdx.x & 31, wid = threadIdx.x >> 5;
    const int warp_m = wid >> 1, warp_n = wid & 1;
    const int quad = lane >> 2, qt = lane & 3;
#pragma unroll
    for (int mt = 0; mt < 2; mt++)
#pragma unroll
        for (int h = 0; h < 2; h++) {
            const int m = row0 + warp_m * 32 + mt * 16 + quad + h * 8;
            float* Orow = out + ((size_t)bz * SEQ + m) * HID;
#pragma unroll
            for (int nt = 0; nt < 8; nt++) {
                const int c = col0 + warp_n * 64 + nt * 8 + qt * 2;
                float2 v; v.x = acc[mt][nt][2 * h]; v.y = acc[mt][nt][2 * h + 1];
                *(float2*)(Orow + c) = v;
            }
        }
}

// ---------------------------------------------------------------------------
extern "C" void kernel_launch(void* const* d_in, const int* in_sizes, int n_in,
                              void* d_out, int out_size)
{
    const float* x = (const float*)d_in[0];
    const float* W = (const float*)d_in[1];
    const float* b = (const float*)d_in[2];
    float* out = (float*)d_out;
    (void)in_sizes; (void)n_in; (void)out_size;

    cudaFuncSetAttribute(qkv_gemm, cudaFuncAttributeMaxDynamicSharedMemorySize, SM_TOTAL);
    cudaFuncSetAttribute(qk_gemm,  cudaFuncAttributeMaxDynamicSharedMemorySize, SM_TOTAL);
    cudaFuncSetAttribute(pv_gemm,  cudaFuncAttributeMaxDynamicSharedMemorySize, SM_TOTAL);

    __nv_bfloat16 *xh, *xl, *wh, *wl;
    cudaGetSymbolAddress((void**)&xh, g_x_hi); cudaGetSymbolAddress((void**)&xl, g_x_lo);
    cudaGetSymbolAddress((void**)&wh, g_w_hi); cudaGetSymbolAddress((void**)&wl, g_w_lo);

    int nx4 = TOK * HID / 4, nw4 = HID3 * HID / 4;
    split_kernel<<<(nx4 + 255) / 256, 256>>>(x, xh, xl, nx4);
    split_kernel<<<(nw4 + 255) / 256, 256>>>(W, wh, wl, nw4);

    qkv_gemm<<<dim3(HID3 / BN, TOK / BM, 1), 256, SM_TOTAL>>>(b);
    qk_gemm<<<dim3(SEQ / BN, SEQ / BM, BATCH), 256, SM_TOTAL>>>();
    softmax_split_kernel<<<TOK, 256>>>();
    pv_gemm<<<dim3(HID / BN, SEQ / BM, BATCH), 256, SM_TOTAL>>>(out);
}

// round 16
// speedup vs baseline: 2.6958x; 1.2408x over previous
#include <cuda_runtime.h>
#include <cuda_bf16.h>
#include <cuda_fp16.h>
#include <cstdint>

#define HID   768
#define HID3  2304
#define SEQ   2048
#define BATCH 8
#define TOK   (BATCH * SEQ)

#define BM 128
#define BN 128
#define BK 64                 // 16-bit elems per chunk = 128 B/row
#define NSTAGE 3
#define STAGE_BYTES 32768     // A 16KB + B 16KB
#define SM_TOTAL (NSTAGE * STAGE_BYTES)   // 96 KB -> 2 CTAs/SM (proven sweet spot)

// ---------------- scratch (__device__ globals, allocation-free rule) ----------------
__device__ __align__(1024) __nv_bfloat16 g_x_hi[(size_t)TOK * HID];
__device__ __align__(1024) __nv_bfloat16 g_x_lo[(size_t)TOK * HID];
__device__ __align__(1024) __half        g_x_f16[(size_t)TOK * HID];
__device__ __align__(1024) __nv_bfloat16 g_w_hi[(size_t)HID3 * HID];
__device__ __align__(1024) __nv_bfloat16 g_w_lo[(size_t)HID3 * HID];
__device__ __align__(1024) __half        g_wv_f16[(size_t)HID * HID];        // W rows [2H,3H)
__device__ __align__(1024) __nv_bfloat16 g_q_hi[(size_t)TOK * HID];
__device__ __align__(1024) __nv_bfloat16 g_q_lo[(size_t)TOK * HID];
__device__ __align__(1024) __nv_bfloat16 g_k_hi[(size_t)TOK * HID];
__device__ __align__(1024) __nv_bfloat16 g_k_lo[(size_t)TOK * HID];
__device__ __align__(1024) __half        g_vT[(size_t)BATCH * HID * SEQ];    // [b][dim][tok]
__device__ __align__(1024) float         g_S[(size_t)BATCH * SEQ * SEQ];
__device__ __align__(1024) __half        g_P[(size_t)TOK * SEQ];

// ---------------- PTX helpers (sm_80-era only: legal on plain sm_103) ----------------
__device__ __forceinline__ uint32_t smem_u32(const void* p) {
    uint32_t a;
    asm("{ .reg .u64 t; cvta.to.shared.u64 t, %1; cvt.u32.u64 %0, t; }" : "=r"(a) : "l"(p));
    return a;
}
__device__ __forceinline__ void cp16(uint32_t dst, const void* src) {
    asm volatile("cp.async.cg.shared.global [%0], [%1], 16;"
                 :: "r"(dst), "l"(__cvta_generic_to_global(src)) : "memory");
}
#define CP_COMMIT() asm volatile("cp.async.commit_group;" ::: "memory")
#define CP_WAIT1()  asm volatile("cp.async.wait_group 1;" ::: "memory")

__device__ __forceinline__ void ldsm_x4(uint32_t& d0, uint32_t& d1, uint32_t& d2,
                                        uint32_t& d3, uint32_t addr) {
    asm volatile("ldmatrix.sync.aligned.m8n8.x4.shared.b16 {%0,%1,%2,%3}, [%4];"
                 : "=r"(d0), "=r"(d1), "=r"(d2), "=r"(d3) : "r"(addr));
}
template <bool FP16>
__device__ __forceinline__ void mma16816(float (&c)[4], uint32_t a0, uint32_t a1,
                                         uint32_t a2, uint32_t a3,
                                         uint32_t b0, uint32_t b1) {
    if (FP16)
        asm volatile("mma.sync.aligned.m16n8k16.row.col.f32.f16.f16.f32 "
                     "{%0,%1,%2,%3}, {%4,%5,%6,%7}, {%8,%9}, {%0,%1,%2,%3};"
                     : "+f"(c[0]), "+f"(c[1]), "+f"(c[2]), "+f"(c[3])
                     : "r"(a0), "r"(a1), "r"(a2), "r"(a3), "r"(b0), "r"(b1));
    else
        asm volatile("mma.sync.aligned.m16n8k16.row.col.f32.bf16.bf16.f32 "
                     "{%0,%1,%2,%3}, {%4,%5,%6,%7}, {%8,%9}, {%0,%1,%2,%3};"
                     : "+f"(c[0]), "+f"(c[1]), "+f"(c[2]), "+f"(c[3])
                     : "r"(a0), "r"(a1), "r"(a2), "r"(a3), "r"(b0), "r"(b1));
}

__device__ __forceinline__ void split1(float v, __nv_bfloat16& h, __nv_bfloat16& l) {
    h = __float2bfloat16(v);
    l = __float2bfloat16(v - __bfloat162float(h));
}

// ---------------------------------------------------------------------------
// Split-GEMM HMMA mainloop (proven config: 3-stage cp.async, wait_group 1,
// regs <= 128 -> 2 CTAs/SM).
//   NCOMBO=3 (bf16x3): (A0,B0),(A1,B0),(A0,B1)   NCOMBO=1: (A0,B0) only.
// A rows at row0.., B rows at bcol0.. (both K-major, 16-bit).
// ---------------------------------------------------------------------------
template <int NCOMBO, bool FP16>
__device__ __forceinline__ void run_mainloop(
    const uint8_t* __restrict__ A0, const uint8_t* __restrict__ A1, int lda,
    const uint8_t* __restrict__ B0, const uint8_t* __restrict__ B1, int ldb,
    int K, int row0, int bcol0, char* smem, float (&acc)[2][8][4])
{
    const int tid  = threadIdx.x;
    const int lane = tid & 31, wid = tid >> 5;
    const int warp_m = wid >> 1, warp_n = wid & 1;
    const uint32_t sb = smem_u32(smem);

#pragma unroll
    for (int mt = 0; mt < 2; mt++)
#pragma unroll
        for (int nt = 0; nt < 8; nt++)
#pragma unroll
            for (int j = 0; j < 4; j++) acc[mt][nt][j] = 0.f;

    const int NIT = NCOMBO * (K / BK);

    auto issue = [&](int it) {
        const int chunk = it / NCOMBO, combo = it - NCOMBO * chunk;
        const uint8_t* A = (NCOMBO == 3 && combo == 1) ? A1 : A0;
        const uint8_t* B = (NCOMBO >= 2 && combo == NCOMBO - 1) ? B1 : B0;
        const size_t k0b = (size_t)chunk * BK * 2;      // byte offset in K
        const uint32_t st = sb + (uint32_t)(it % NSTAGE) * STAGE_BYTES;
#pragma unroll
        for (int w = 0; w < 4; w++) {
            int idx = tid + w * 256, r = idx >> 3, c8 = idx & 7;
            cp16(st + r * 128 + ((c8 ^ (r & 7)) << 4),
                 A + (size_t)(row0 + r) * lda * 2 + k0b + c8 * 16);
        }
#pragma unroll
        for (int w = 0; w < 4; w++) {
            int idx = tid + w * 256, r = idx >> 3, c8 = idx & 7;
            cp16(st + 16384 + r * 128 + ((c8 ^ (r & 7)) << 4),
                 B + (size_t)(bcol0 + r) * ldb * 2 + k0b + c8 * 16);
        }
    };

    issue(0); CP_COMMIT();
    issue(1); CP_COMMIT();

    // per-thread ldmatrix address invariants
    const int rowA = warp_m * 32 + (lane & 15);     // + mt*16 (keeps r&7)
    const int hA   = lane >> 4, sA7 = rowA & 7;
    const int rB   = warp_n * 64 + (lane & 7) + ((lane >> 4) << 3);  // + p*16
    const int hB   = (lane >> 3) & 1, sB7 = lane & 7;

    for (int it = 0; it < NIT; it++) {
        CP_WAIT1();
        __syncthreads();
        if (it + 2 < NIT) issue(it + 2);
        CP_COMMIT();

        const uint32_t sA  = sb + (uint32_t)(it % NSTAGE) * STAGE_BYTES;
        const uint32_t sBs = sA + 16384;
#pragma unroll
        for (int k16 = 0; k16 < 4; k16++) {
            uint32_t a[2][4], b[4][4];
#pragma unroll
            for (int mt = 0; mt < 2; mt++)
                ldsm_x4(a[mt][0], a[mt][1], a[mt][2], a[mt][3],
                        sA + (rowA + mt * 16) * 128 + (((k16 * 2 + hA) ^ sA7) << 4));
#pragma unroll
            for (int p = 0; p < 4; p++)
                ldsm_x4(b[p][0], b[p][1], b[p][2], b[p][3],
                        sBs + (rB + p * 16) * 128 + (((k16 * 2 + hB) ^ sB7) << 4));
#pragma unroll
            for (int mt = 0; mt < 2; mt++)
#pragma unroll
                for (int nt = 0; nt < 8; nt++)
                    mma16816<FP16>(acc[mt][nt], a[mt][0], a[mt][1], a[mt][2], a[mt][3],
                                   b[nt >> 1][(nt & 1) * 2], b[nt >> 1][(nt & 1) * 2 + 1]);
        }
    }
}

// ---------------- stage 0a: x -> bf16 hi/lo + fp16 ----------------
__global__ __launch_bounds__(256) void split_x_kernel(
    const float* __restrict__ src, int n4)
{
    int i = blockIdx.x * 256 + threadIdx.x;
    if (i >= n4) return;
    float4 v = ((const float4*)src)[i];
    __nv_bfloat16 h0, l0, h1, l1, h2, l2, h3, l3;
    split1(v.x, h0, l0); split1(v.y, h1, l1);
    split1(v.z, h2, l2); split1(v.w, h3, l3);
    __nv_bfloat162* H = (__nv_bfloat162*)g_x_hi;
    __nv_bfloat162* L = (__nv_bfloat162*)g_x_lo;
    H[2 * i]     = __nv_bfloat162(h0, h1);
    H[2 * i + 1] = __nv_bfloat162(h2, h3);
    L[2 * i]     = __nv_bfloat162(l0, l1);
    L[2 * i + 1] = __nv_bfloat162(l2, l3);
    __half2* F = (__half2*)g_x_f16;
    F[2 * i]     = __floats2half2_rn(v.x, v.y);
    F[2 * i + 1] = __floats2half2_rn(v.z, v.w);
}

// ---------------- stage 0b: W -> bf16 hi/lo (q/k rows) + fp16 (v rows) ----------------
__global__ __launch_bounds__(256) void split_w_kernel(
    const float* __restrict__ W, int n4)
{
    int i = blockIdx.x * 256 + threadIdx.x;
    if (i >= n4) return;
    float4 v = ((const float4*)W)[i];
    __nv_bfloat16 h0, l0, h1, l1, h2, l2, h3, l3;
    split1(v.x, h0, l0); split1(v.y, h1, l1);
    split1(v.z, h2, l2); split1(v.w, h3, l3);
    __nv_bfloat162* H = (__nv_bfloat162*)g_w_hi;
    __nv_bfloat162* L = (__nv_bfloat162*)g_w_lo;
    H[2 * i]     = __nv_bfloat162(h0, h1);
    H[2 * i + 1] = __nv_bfloat162(h2, h3);
    L[2 * i]     = __nv_bfloat162(l0, l1);
    L[2 * i + 1] = __nv_bfloat162(l2, l3);
    const int vstart4 = 2 * HID * HID / 4;     // first float4 index of v rows
    if (i >= vstart4) {
        __half2* F = (__half2*)g_wv_f16;
        int j = i - vstart4;
        F[2 * j]     = __floats2half2_rn(v.x, v.y);
        F[2 * j + 1] = __floats2half2_rn(v.z, v.w);
    }
}

// ---------------- stage 1: QKV = x @ W^T + b ----------------
// q/k col-tiles: bf16x3. v col-tiles: single-pass fp16 (x_f16 * Wv_f16),
// staged in smem and stored transposed (coalesced) as single fp16 vT.
#define VT_PITCH 136   // elems; 272 B row pitch (16B aligned, conflict-skewed)

__global__ __launch_bounds__(256) void qkv_gemm(const float* __restrict__ bias)
{
    extern __shared__ char smem[];
    const int row0 = blockIdx.y * BM;
    const int col0 = blockIdx.x * BN;
    float acc[2][8][4];

    const int tid = threadIdx.x;
    const int lane = tid & 31, wid = tid >> 5;
    const int warp_m = wid >> 1, warp_n = wid & 1;
    const int quad = lane >> 2, qt = lane & 3;

    if (col0 < 2 * HID) {
        run_mainloop<3, false>((const uint8_t*)g_x_hi, (const uint8_t*)g_x_lo, HID,
                               (const uint8_t*)g_w_hi, (const uint8_t*)g_w_lo, HID,
                               HID, row0, col0, smem, acc);
        __nv_bfloat16* dh = (col0 < HID) ? g_q_hi : g_k_hi;
        __nv_bfloat16* dl = (col0 < HID) ? g_q_lo : g_k_lo;
        const int cbase = (col0 < HID) ? col0 : (col0 - HID);
#pragma unroll
        for (int mt = 0; mt < 2; mt++)
#pragma unroll
            for (int h = 0; h < 2; h++) {
                const int t = row0 + warp_m * 32 + mt * 16 + quad + h * 8;
#pragma unroll
                for (int nt = 0; nt < 8; nt++) {
                    const int lcol = warp_n * 64 + nt * 8 + qt * 2;
                    float v0 = acc[mt][nt][2 * h]     + __ldg(bias + col0 + lcol);
                    float v1 = acc[mt][nt][2 * h + 1] + __ldg(bias + col0 + lcol + 1);
                    __nv_bfloat16 h0, l0, h1, l1;
                    split1(v0, h0, l0); split1(v1, h1, l1);
                    size_t o = (size_t)t * HID + cbase + lcol;
                    *(__nv_bfloat162*)(dh + o) = __nv_bfloat162(h0, h1);
                    *(__nv_bfloat162*)(dl + o) = __nv_bfloat162(l0, l1);
                }
            }
    } else {
        // ---- v tile: 1-pass fp16 GEMM, then transposed coalesced fp16 store ----
        run_mainloop<1, true>((const uint8_t*)g_x_f16, nullptr, HID,
                              (const uint8_t*)g_wv_f16, nullptr, HID,
                              HID, row0, col0 - 2 * HID, smem, acc);
        __syncthreads();    // all warps done reading stage buffers
        __half* sv = (__half*)smem;                          // [128][VT_PITCH]
#pragma unroll
        for (int mt = 0; mt < 2; mt++)
#pragma unroll
            for (int h = 0; h < 2; h++) {
                const int r = warp_m * 32 + mt * 16 + quad + h * 8;   // local token
#pragma unroll
                for (int nt = 0; nt < 8; nt++) {
                    const int lcol = warp_n * 64 + nt * 8 + qt * 2;   // local dim
                    float v0 = acc[mt][nt][2 * h]     + __ldg(bias + col0 + lcol);
                    float v1 = acc[mt][nt][2 * h + 1] + __ldg(bias + col0 + lcol + 1);
                    sv[lcol * VT_PITCH + r]       = __float2half(v0);
                    sv[(lcol + 1) * VT_PITCH + r] = __float2half(v1);
                }
            }
        __syncthreads();
        const int bz = row0 >> 11, tr0 = row0 & 2047;
        const int d0 = col0 - 2 * HID;
        const int d = tid >> 1, half_ = tid & 1;     // 128 dims x 2 64-tok halves
        const size_t go = ((size_t)bz * HID + d0 + d) * SEQ + tr0 + half_ * 64;
        const uint4* s4 = (const uint4*)(sv + d * VT_PITCH + half_ * 64);
        uint4* g4 = (uint4*)(g_vT + go);
#pragma unroll
        for (int u = 0; u < 8; u++) g4[u] = s4[u];
    }
}

// ---------------- stage 2: S = q @ k^T (per batch) ----------------
__global__ __launch_bounds__(256) void qk_gemm()
{
    extern __shared__ char smem[];
    const int bz = blockIdx.z;
    const size_t off = (size_t)bz * SEQ * HID;
    const int row0 = blockIdx.y * BM;
    const int col0 = blockIdx.x * BN;
    float acc[2][8][4];
    run_mainloop<3, false>((const uint8_t*)(g_q_hi + off), (const uint8_t*)(g_q_lo + off), HID,
                           (const uint8_t*)(g_k_hi + off), (const uint8_t*)(g_k_lo + off), HID,
                           HID, row0, col0, smem, acc);

    const int lane = threadIdx.x & 31, wid = threadIdx.x >> 5;
    const int warp_m = wid >> 1, warp_n = wid & 1;
    const int quad = lane >> 2, qt = lane & 3;
#pragma unroll
    for (int mt = 0; mt < 2; mt++)
#pragma unroll
        for (int h = 0; h < 2; h++) {
            const int m = row0 + warp_m * 32 + mt * 16 + quad + h * 8;
            float* Srow = g_S + ((size_t)bz * SEQ + m) * SEQ;
#pragma unroll
            for (int nt = 0; nt < 8; nt++) {
                const int c = col0 + warp_n * 64 + nt * 8 + qt * 2;
                float2 v; v.x = acc[mt][nt][2 * h]; v.y = acc[mt][nt][2 * h + 1];
                *(float2*)(Srow + c) = v;
            }
        }
}

// ---------------- stage 3: softmax -> fp16 P ----------------
__global__ __launch_bounds__(256) void softmax_split_kernel()
{
    const size_t row = blockIdx.x;
    const float4* p4 = (const float4*)(g_S + row * SEQ);
    const int tid = threadIdx.x;
    float4 v0 = p4[tid];
    float4 v1 = p4[tid + 256];

    float m = fmaxf(fmaxf(fmaxf(v0.x, v0.y), fmaxf(v0.z, v0.w)),
                    fmaxf(fmaxf(v1.x, v1.y), fmaxf(v1.z, v1.w)));
    __shared__ float red[8], red2[8];
#pragma unroll
    for (int o = 16; o; o >>= 1) m = fmaxf(m, __shfl_xor_sync(0xffffffffu, m, o));
    if ((tid & 31) == 0) red[tid >> 5] = m;
    __syncthreads();
    float bm = red[0];
#pragma unroll
    for (int i = 1; i < 8; i++) bm = fmaxf(bm, red[i]);

    v0.x = __expf(v0.x - bm); v0.y = __expf(v0.y - bm);
    v0.z = __expf(v0.z - bm); v0.w = __expf(v0.w - bm);
    v1.x = __expf(v1.x - bm); v1.y = __expf(v1.y - bm);
    v1.z = __expf(v1.z - bm); v1.w = __expf(v1.w - bm);

    float s = ((v0.x + v0.y) + (v0.z + v0.w)) + ((v1.x + v1.y) + (v1.z + v1.w));
#pragma unroll
    for (int o = 16; o; o >>= 1) s += __shfl_xor_sync(0xffffffffu, s, o);
    if ((tid & 31) == 0) red2[tid >> 5] = s;
    __syncthreads();
    float ts = red2[0];
#pragma unroll
    for (int i = 1; i < 8; i++) ts += red2[i];
    const float inv = 1.0f / ts;

    __half2* P2 = (__half2*)(g_P + row * SEQ);
    P2[2 * tid]     = __floats2half2_rn(v0.x * inv, v0.y * inv);
    P2[2 * tid + 1] = __floats2half2_rn(v0.z * inv, v0.w * inv);
    P2[2 * (tid + 256)]     = __floats2half2_rn(v1.x * inv, v1.y * inv);
    P2[2 * (tid + 256) + 1] = __floats2half2_rn(v1.z * inv, v1.w * inv);
}

// ---------------- stage 4: out = P @ v (single-pass fp16) ----------------
__global__ __launch_bounds__(256) void pv_gemm(float* __restrict__ out)
{
    extern __shared__ char smem[];
    const int bz = blockIdx.z;
    const size_t pOff = (size_t)bz * SEQ * SEQ;
    const size_t vOff = (size_t)bz * HID * SEQ;
    const int row0 = blockIdx.y * BM;
    const int col0 = blockIdx.x * BN;
    float acc[2][8][4];
    run_mainloop<1, true>((const uint8_t*)(g_P + pOff), nullptr, SEQ,
                          (const uint8_t*)(g_vT + vOff), nullptr, SEQ,
                          SEQ, row0, col0, smem, acc);

    const int lane = threadIdx.x & 31, wid = threadIdx.x >> 5;
    const int warp_m = wid >> 1, warp_n = wid & 1;
    const int quad = lane >> 2, qt = lane & 3;
#pragma unroll
    for (int mt = 0; mt < 2; mt++)
#pragma unroll
        for (int h = 0; h < 2; h++) {
            const int m = row0 + warp_m * 32 + mt * 16 + quad + h * 8;
            float* Orow = out + ((size_t)bz * SEQ + m) * HID;
#pragma unroll
            for (int nt = 0; nt < 8; nt++) {
                const int c = col0 + warp_n * 64 + nt * 8 + qt * 2;
                float2 v; v.x = acc[mt][nt][2 * h]; v.y = acc[mt][nt][2 * h + 1];
                *(float2*)(Orow + c) = v;
            }
        }
}

// ---------------------------------------------------------------------------
extern "C" void kernel_launch(void* const* d_in, const int* in_sizes, int n_in,
                              void* d_out, int out_size)
{
    const float* x = (const float*)d_in[0];
    const float* W = (const float*)d_in[1];
    const float* b = (const float*)d_in[2];
    float* out = (float*)d_out;
    (void)in_sizes; (void)n_in; (void)out_size;

    cudaFuncSetAttribute(qkv_gemm, cudaFuncAttributeMaxDynamicSharedMemorySize, SM_TOTAL);
    cudaFuncSetAttribute(qk_gemm,  cudaFuncAttributeMaxDynamicSharedMemorySize, SM_TOTAL);
    cudaFuncSetAttribute(pv_gemm,  cudaFuncAttributeMaxDynamicSharedMemorySize, SM_TOTAL);

    int nx4 = TOK * HID / 4, nw4 = HID3 * HID / 4;
    split_x_kernel<<<(nx4 + 255) / 256, 256>>>(x, nx4);
    split_w_kernel<<<(nw4 + 255) / 256, 256>>>(W, nw4);

    qkv_gemm<<<dim3(HID3 / BN, TOK / BM, 1), 256, SM_TOTAL>>>(b);
    qk_gemm<<<dim3(SEQ / BN, SEQ / BM, BATCH), 256, SM_TOTAL>>>();
    softmax_split_kernel<<<TOK, 256>>>();
    pv_gemm<<<dim3(HID / BN, SEQ / BM, BATCH), 256, SM_TOTAL>>>(out);
}